// round 4
// baseline (speedup 1.0000x reference)
#include <cuda_runtime.h>
#include <math.h>

#define Dm    256
#define Kc    128
#define NTOK  131072
#define TM    256          // tokens per block
#define DC    32           // D-chunk per smem stage
#define PA    260          // A-tile pitch (tokens dim), mult of 4
#define NBLK  (NTOK / TM)  // 512

#define SMEM_BYTES ((2*DC*PA + Dm*Kc) * 4 + TM*4 + Kc*4 + 256*4)

// output layout (float32, tuple order flattened+concatenated)
// [0]=loss, [1 .. 1+N*D)=quantized, [1+N*D]=perplexity,
// [2+N*D .. 2+N*D+N*K)=encodings, then indices (as float)
#define OFF_Q    ((size_t)1)
#define OFF_PERP ((size_t)1 + (size_t)NTOK * Dm)
#define OFF_ENC  (OFF_PERP + 1)
#define OFF_IDX  (OFF_ENC + (size_t)NTOK * Kc)

__device__ int   g_counts[Kc];
__device__ float g_ek2[Kc];
__device__ float g_partials[NBLK];

union F2 { float2 f; unsigned long long u; };

__device__ __forceinline__ void fma2(unsigned long long& c, unsigned long long a, unsigned long long b) {
    asm("fma.rn.f32x2 %0, %1, %2, %0;" : "+l"(c) : "l"(a), "l"(b));
}

// ---------------- init: zero counts, precompute ||e_k||^2 ----------------
__global__ void vq_init_kernel(const float* __restrict__ emb) {
    int t = threadIdx.x;                 // 512 threads
    if (t < Kc) g_counts[t] = 0;
    int code = t >> 2, part = t & 3;     // 4 threads per code
    const float* row = emb + code * Dm + part * 64;
    float s = 0.f;
    #pragma unroll 8
    for (int i = 0; i < 64; i++) { float v = row[i]; s = fmaf(v, v, s); }
    s += __shfl_xor_sync(0xffffffffu, s, 1);
    s += __shfl_xor_sync(0xffffffffu, s, 2);
    if (part == 0) g_ek2[code] = s;
}

// ---------------- main: GEMM + argmin + all large outputs ----------------
extern __shared__ float smem[];

__global__ void __launch_bounds__(256, 1) vq_main_kernel(
    const float* __restrict__ inp,
    const float* __restrict__ emb,
    float* __restrict__ out)
{
    float* As   = smem;                        // [2][DC][PA]  (d-major, token minor)
    float* Bs   = smem + 2 * DC * PA;          // [Dm][Kc]     (d-major, code minor)
    int*   sidx = (int*)(Bs + Dm * Kc);        // [TM]
    int*   hist = sidx + TM;                   // [Kc]
    float* red  = (float*)(hist + Kc);         // [256]

    const int tid = threadIdx.x;
    const int tx  = tid & 15;
    const int ty  = tid >> 4;
    const int ty16 = ty * 16;
    const int tx4  = tx * 4;
    const int tokBase = blockIdx.x * TM;

    // ---- load codebook transposed: emb[code][d] -> Bs[d][code] ----
    for (int i = tid; i < Kc * (Dm / 4); i += 256) {   // 8192 float4
        int code = i >> 6;
        int f4   = i & 63;
        float4 v = *(const float4*)(emb + code * Dm + f4 * 4);
        int d = f4 * 4;
        Bs[(d + 0) * Kc + code] = v.x;
        Bs[(d + 1) * Kc + code] = v.y;
        Bs[(d + 2) * Kc + code] = v.z;
        Bs[(d + 3) * Kc + code] = v.w;
    }

    // ---- prefetch input chunk 0 and store transposed ----
    const int lf4  = tid & 7;    // float4 index inside 32-float chunk
    const int ltok = tid >> 3;   // 0..31
    float4 r[8];
    #pragma unroll
    for (int q = 0; q < 8; q++) {
        int tok = ltok + q * 32;
        r[q] = *(const float4*)(inp + (tokBase + tok) * Dm + lf4 * 4);
    }
    #pragma unroll
    for (int q = 0; q < 8; q++) {
        int tok = ltok + q * 32;
        As[(lf4 * 4 + 0) * PA + tok] = r[q].x;
        As[(lf4 * 4 + 1) * PA + tok] = r[q].y;
        As[(lf4 * 4 + 2) * PA + tok] = r[q].z;
        As[(lf4 * 4 + 3) * PA + tok] = r[q].w;
    }
    __syncthreads();

    // ---- accumulators: 8 token-pairs x 8 codes, packed f32x2 ----
    unsigned long long acc[8][8];
    #pragma unroll
    for (int p = 0; p < 8; p++)
        #pragma unroll
        for (int cc = 0; cc < 8; cc++) acc[p][cc] = 0ull;

    #pragma unroll 1
    for (int c = 0; c < Dm / DC; c++) {
        if (c < Dm / DC - 1) {       // prefetch next chunk (global -> regs)
            #pragma unroll
            for (int q = 0; q < 8; q++) {
                int tok = ltok + q * 32;
                r[q] = *(const float4*)(inp + (tokBase + tok) * Dm + (c + 1) * DC + lf4 * 4);
            }
        }
        const float* Ac = As + (c & 1) * DC * PA;
        #pragma unroll 8
        for (int k = 0; k < DC; k++) {
            const float* ar = Ac + k * PA + ty16;
            float4 a0 = *(const float4*)(ar);
            float4 a1 = *(const float4*)(ar + 4);
            float4 a2 = *(const float4*)(ar + 8);
            float4 a3 = *(const float4*)(ar + 12);
            const float* br = Bs + (c * DC + k) * Kc + tx4;
            float4 b0 = *(const float4*)(br);
            float4 b1 = *(const float4*)(br + 64);
            F2 av[8];
            av[0].f = make_float2(a0.x, a0.y); av[1].f = make_float2(a0.z, a0.w);
            av[2].f = make_float2(a1.x, a1.y); av[3].f = make_float2(a1.z, a1.w);
            av[4].f = make_float2(a2.x, a2.y); av[5].f = make_float2(a2.z, a2.w);
            av[6].f = make_float2(a3.x, a3.y); av[7].f = make_float2(a3.z, a3.w);
            float bb[8] = {b0.x, b0.y, b0.z, b0.w, b1.x, b1.y, b1.z, b1.w};
            #pragma unroll
            for (int cc = 0; cc < 8; cc++) {
                F2 bd; bd.f = make_float2(bb[cc], bb[cc]);
                #pragma unroll
                for (int p = 0; p < 8; p++) fma2(acc[p][cc], av[p].u, bd.u);
            }
        }
        if (c < Dm / DC - 1) {       // stage prefetched chunk
            float* An = As + ((c + 1) & 1) * DC * PA;
            #pragma unroll
            for (int q = 0; q < 8; q++) {
                int tok = ltok + q * 32;
                An[(lf4 * 4 + 0) * PA + tok] = r[q].x;
                An[(lf4 * 4 + 1) * PA + tok] = r[q].y;
                An[(lf4 * 4 + 2) * PA + tok] = r[q].z;
                An[(lf4 * 4 + 3) * PA + tok] = r[q].w;
            }
        }
        __syncthreads();
    }

    // ---- argmin over codes: score = ||e||^2 - 2*dot  (||x||^2 constant) ----
    float e2[8];
    #pragma unroll
    for (int j = 0; j < 4; j++) {
        e2[j]     = g_ek2[tx4 + j];
        e2[4 + j] = g_ek2[64 + tx4 + j];
    }
    #pragma unroll
    for (int t = 0; t < 16; t++) {
        float best = 3.402823466e38f;
        int   bi   = 0;
        #pragma unroll
        for (int cc = 0; cc < 8; cc++) {
            F2 a; a.u = acc[t >> 1][cc];
            float dot = (t & 1) ? a.f.y : a.f.x;
            float s = fmaf(-2.0f, dot, e2[cc]);
            int code = (cc < 4) ? (tx4 + cc) : (64 + tx4 + (cc - 4));
            if (s < best) { best = s; bi = code; }   // ascending code order -> first-min
        }
        #pragma unroll
        for (int m = 1; m < 16; m <<= 1) {
            float ov = __shfl_xor_sync(0xffffffffu, best, m);
            int   oi = __shfl_xor_sync(0xffffffffu, bi,   m);
            if (ov < best || (ov == best && oi < bi)) { best = ov; bi = oi; }
        }
        if (tx == 0) sidx[ty16 + t] = bi;
    }
    __syncthreads();

    // ---- histogram -> global counts ----
    if (tid < Kc) hist[tid] = 0;
    __syncthreads();
    atomicAdd(&hist[sidx[tid]], 1);          // 256 threads == 256 tokens
    __syncthreads();
    if (tid < Kc) atomicAdd(&g_counts[tid], hist[tid]);

    // ---- quantized output + loss terms (direct (e-x)^2, matches reference) ----
    // NOTE: out_q region starts at element offset 1 (mod 4 != 0) -> scalar stores.
    float lsum = 0.f;
    float* out_q = out + OFF_Q;
    for (int i = tid; i < TM * (Dm / 4); i += 256) {   // 64 iters
        int tok = i >> 6, f4 = i & 63;
        int k = sidx[tok];
        float4 e = *(const float4*)(emb + k * Dm + f4 * 4);          // 16B aligned
        float4 x = *(const float4*)(inp + (tokBase + tok) * Dm + f4 * 4);
        float* qp = out_q + (size_t)(tokBase + tok) * Dm + f4 * 4;   // unaligned for v4
        qp[0] = e.x; qp[1] = e.y; qp[2] = e.z; qp[3] = e.w;
        float dx = e.x - x.x, dy = e.y - x.y, dz = e.z - x.z, dw = e.w - x.w;
        lsum += dx * dx + dy * dy + dz * dz + dw * dw;
    }

    // ---- one-hot encodings (region start ≡ 2 mod 4 -> float2 stores are 8B aligned) ----
    float* out_e = out + OFF_ENC;
    for (int i = tid; i < TM * (Kc / 4); i += 256) {   // 32 iters
        int tok = i >> 5, f4 = i & 31;
        int k = sidx[tok];
        int d0 = f4 * 4;
        float2 v01, v23;
        v01.x = (d0 + 0 == k) ? 1.f : 0.f;
        v01.y = (d0 + 1 == k) ? 1.f : 0.f;
        v23.x = (d0 + 2 == k) ? 1.f : 0.f;
        v23.y = (d0 + 3 == k) ? 1.f : 0.f;
        float* ep = out_e + (size_t)tok * Kc + d0 + (size_t)tokBase * Kc;
        *(float2*)(ep)     = v01;
        *(float2*)(ep + 2) = v23;
    }

    // ---- indices (as float) ----
    out[OFF_IDX + tokBase + tid] = (float)sidx[tid];

    // ---- deterministic block-level loss partial ----
    red[tid] = lsum;
    __syncthreads();
    #pragma unroll
    for (int s = 128; s > 0; s >>= 1) {
        if (tid < s) red[tid] += red[tid + s];
        __syncthreads();
    }
    if (tid == 0) g_partials[blockIdx.x] = red[0];
}

// ---------------- final: loss + perplexity ----------------
__global__ void vq_final_kernel(float* __restrict__ out) {
    __shared__ float sm[512];
    int t = threadIdx.x;     // 512 threads
    sm[t] = g_partials[t];
    __syncthreads();
    #pragma unroll
    for (int s = 256; s > 0; s >>= 1) {
        if (t < s) sm[t] += sm[t + s];
        __syncthreads();
    }
    float esum = sm[0];
    __syncthreads();

    float term = 0.f;
    if (t < Kc) {
        float p = (float)g_counts[t] / (float)NTOK;
        term = p * logf(p + 1e-10f);
    }
    sm[t] = term;
    __syncthreads();
    #pragma unroll
    for (int s = 256; s > 0; s >>= 1) {
        if (t < s) sm[t] += sm[t + s];
        __syncthreads();
    }
    if (t == 0) {
        out[0]        = 0.25f * esum / ((float)NTOK * (float)Dm);  // commitment loss
        out[OFF_PERP] = expf(-sm[0]);                              // perplexity
    }
}

// ---------------- launch ----------------
extern "C" void kernel_launch(void* const* d_in, const int* in_sizes, int n_in,
                              void* d_out, int out_size) {
    const float* inp = (const float*)d_in[0];   // [64,2048,256] f32
    const float* emb = (const float*)d_in[1];   // [128,256]     f32
    float* out = (float*)d_out;

    cudaFuncSetAttribute(vq_main_kernel,
                         cudaFuncAttributeMaxDynamicSharedMemorySize, SMEM_BYTES);

    vq_init_kernel<<<1, 512>>>(emb);
    vq_main_kernel<<<NBLK, 256, SMEM_BYTES>>>(inp, emb, out);
    vq_final_kernel<<<1, 512>>>(out);
}

// round 5
// speedup vs baseline: 1.3521x; 1.3521x over previous
#include <cuda_runtime.h>
#include <math.h>

#define Dm     256
#define Kc     128
#define NTOK   131072
#define TM     128                 // tokens per tile
#define DC     32                  // D-chunk per smem stage
#define PA     132                 // A-tile pitch (tokens dim)
#define NTILES (NTOK / TM)         // 1024
#define MAXCTA 160

// output layout (float32, tuple order flattened+concatenated)
#define OFF_Q    ((size_t)1)
#define OFF_PERP ((size_t)1 + (size_t)NTOK * Dm)
#define OFF_ENC  (OFF_PERP + 1)
#define OFF_IDX  (OFF_ENC + (size_t)NTOK * Kc)

__device__ int   g_hist[MAXCTA * Kc];
__device__ float g_partials[MAXCTA];
__device__ int   g_done = 0;

union F2 { float2 f; unsigned long long u; };

__device__ __forceinline__ void fma2(unsigned long long& c, unsigned long long a, unsigned long long b) {
    asm("fma.rn.f32x2 %0, %1, %2, %0;" : "+l"(c) : "l"(a), "l"(b));
}

// smem layout (floats):
//  As   [2][DC][PA]  = 8448
//  Bs   [Dm][Kc] swizzled = 32768
//  e2s  [Kc], xn2s [TM], red [256], sidx int[TM], chist int[Kc], ticket int[1]
#define SMEM_FLOATS (2*DC*PA + Dm*Kc + Kc + TM + 256 + TM + Kc + 4)
#define SMEM_BYTES  (SMEM_FLOATS * 4)

extern __shared__ float smem[];

__global__ void __launch_bounds__(256, 1) vq_kernel(
    const float* __restrict__ inp,
    const float* __restrict__ emb,
    float* __restrict__ out,
    int ncta)
{
    float* As   = smem;
    float* Bs   = smem + 2 * DC * PA;
    float* e2s  = Bs + Dm * Kc;
    float* xn2s = e2s + Kc;
    float* red  = xn2s + TM;
    int*   sidx = (int*)(red + 256);
    int*   chist = sidx + TM;
    int*   ticket = chist + Kc;

    const int tid = threadIdx.x;
    const int tx  = tid & 15;          // code group
    const int ty  = tid >> 4;          // token group (8 tokens each)
    const int lf4 = tid & 7;           // float4 slot within 32-float chunk
    const int lt  = tid >> 3;          // 0..31 token lane for staging
    const int cta = blockIdx.x;

    if (tid < Kc) chist[tid] = 0;

    // ---- stage codebook once, swizzled: word(d,c) = d*Kc + (((c>>2)^((d>>2)&31))<<2) + (c&3)
    for (int i = tid; i < Kc * (Dm / 4); i += 256) {
        int code = i >> 6;
        int f4   = i & 63;                      // d = f4*4 + j, so d>>2 == f4
        float4 v = *(const float4*)(emb + code * Dm + f4 * 4);
        int slot = (code >> 2) ^ (f4 & 31);
        float* p = Bs + (f4 * 4) * Kc + (slot << 2) + (code & 3);
        p[0]      = v.x;
        p[Kc]     = v.y;
        p[2 * Kc] = v.z;
        p[3 * Kc] = v.w;
    }
    __syncthreads();

    // ---- ||e_k||^2 from smem (2 threads per code) ----
    {
        int code = tid >> 1, half = tid & 1;
        int c2 = code >> 2, cl = code & 3;
        float s = 0.f;
        #pragma unroll 8
        for (int i = 0; i < 128; i++) {
            int d = half * 128 + i;
            int slot = c2 ^ ((d >> 2) & 31);
            float v = Bs[d * Kc + (slot << 2) + cl];
            s = fmaf(v, v, s);
        }
        s += __shfl_xor_sync(0xffffffffu, s, 1);
        if (half == 0) e2s[code] = s;
    }
    __syncthreads();

    float e2r[8];
    #pragma unroll
    for (int j = 0; j < 4; j++) {
        e2r[j]     = e2s[tx * 4 + j];
        e2r[4 + j] = e2s[64 + tx * 4 + j];
    }

    float lsum = 0.f;

    // ================= persistent tile loop =================
    for (int tile = cta; tile < NTILES; tile += ncta) {
        const int tb = tile * TM;
        float4 r[4];
        float  xsq[4];

        // ---- chunk 0: load + stage + x^2 partials ----
        #pragma unroll
        for (int q = 0; q < 4; q++)
            r[q] = *(const float4*)(inp + (size_t)(tb + lt + 32 * q) * Dm + lf4 * 4);
        #pragma unroll
        for (int q = 0; q < 4; q++) {
            int tok = lt + 32 * q;
            As[(lf4 * 4 + 0) * PA + tok] = r[q].x;
            As[(lf4 * 4 + 1) * PA + tok] = r[q].y;
            As[(lf4 * 4 + 2) * PA + tok] = r[q].z;
            As[(lf4 * 4 + 3) * PA + tok] = r[q].w;
            float s = r[q].x * r[q].x;
            s = fmaf(r[q].y, r[q].y, s);
            s = fmaf(r[q].z, r[q].z, s);
            xsq[q] = fmaf(r[q].w, r[q].w, s);
        }
        __syncthreads();

        unsigned long long acc[4][8];
        #pragma unroll
        for (int p = 0; p < 4; p++)
            #pragma unroll
            for (int cc = 0; cc < 8; cc++) acc[p][cc] = 0ull;

        #pragma unroll 1
        for (int c = 0; c < Dm / DC; c++) {
            if (c < Dm / DC - 1) {
                #pragma unroll
                for (int q = 0; q < 4; q++)
                    r[q] = *(const float4*)(inp + (size_t)(tb + lt + 32 * q) * Dm
                                            + (c + 1) * DC + lf4 * 4);
            }
            const float* Ac = As + (c & 1) * DC * PA;
            #pragma unroll 4
            for (int k = 0; k < DC; k++) {
                const float* ar = Ac + k * PA + ty * 8;
                float4 a0 = *(const float4*)(ar);
                float4 a1 = *(const float4*)(ar + 4);
                int d  = c * DC + k;
                int sl = (tx ^ ((d >> 2) & 31)) << 2;
                const float* br = Bs + d * Kc + sl;
                float4 b0 = *(const float4*)(br);
                float4 b1 = *(const float4*)(Bs + d * Kc + (sl ^ 64));
                F2 av[4];
                av[0].f = make_float2(a0.x, a0.y);
                av[1].f = make_float2(a0.z, a0.w);
                av[2].f = make_float2(a1.x, a1.y);
                av[3].f = make_float2(a1.z, a1.w);
                float bb[8] = {b0.x, b0.y, b0.z, b0.w, b1.x, b1.y, b1.z, b1.w};
                #pragma unroll
                for (int cc = 0; cc < 8; cc++) {
                    F2 bd; bd.f = make_float2(bb[cc], bb[cc]);
                    #pragma unroll
                    for (int p = 0; p < 4; p++) fma2(acc[p][cc], av[p].u, bd.u);
                }
            }
            if (c < Dm / DC - 1) {
                float* An = As + ((c + 1) & 1) * DC * PA;
                #pragma unroll
                for (int q = 0; q < 4; q++) {
                    int tok = lt + 32 * q;
                    An[(lf4 * 4 + 0) * PA + tok] = r[q].x;
                    An[(lf4 * 4 + 1) * PA + tok] = r[q].y;
                    An[(lf4 * 4 + 2) * PA + tok] = r[q].z;
                    An[(lf4 * 4 + 3) * PA + tok] = r[q].w;
                    float s = r[q].x * r[q].x;
                    s = fmaf(r[q].y, r[q].y, s);
                    s = fmaf(r[q].z, r[q].z, s);
                    xsq[q] += fmaf(r[q].w, r[q].w, s);
                }
            }
            __syncthreads();
        }

        // ---- ||x||^2 per token -> smem ----
        #pragma unroll
        for (int q = 0; q < 4; q++) {
            float s = xsq[q];
            s += __shfl_xor_sync(0xffffffffu, s, 1);
            s += __shfl_xor_sync(0xffffffffu, s, 2);
            s += __shfl_xor_sync(0xffffffffu, s, 4);
            if (lf4 == 0) xn2s[lt + 32 * q] = s;
        }

        // ---- argmin per token: score = ||e||^2 - 2 dot ----
        float bsum = 0.f;
        #pragma unroll
        for (int t = 0; t < 8; t++) {
            float best = 3.402823466e38f;
            int   bi   = 0;
            #pragma unroll
            for (int cc = 0; cc < 8; cc++) {
                F2 a; a.u = acc[t >> 1][cc];
                float dot = (t & 1) ? a.f.y : a.f.x;
                float s = fmaf(-2.0f, dot, e2r[cc]);
                int code = (cc < 4) ? (tx * 4 + cc) : (64 + tx * 4 + (cc - 4));
                if (s < best) { best = s; bi = code; }
            }
            #pragma unroll
            for (int m = 1; m < 16; m <<= 1) {
                float ov = __shfl_xor_sync(0xffffffffu, best, m);
                int   oi = __shfl_xor_sync(0xffffffffu, bi,   m);
                if (ov < best || (ov == best && oi < bi)) { best = ov; bi = oi; }
            }
            if (tx == 0) { sidx[ty * 8 + t] = bi; bsum += best; }
        }
        __syncthreads();

        // loss: ||e-x||^2 = best + ||x||^2
        if (tx == 0) {
            #pragma unroll
            for (int t = 0; t < 8; t++) lsum += xn2s[ty * 8 + t];
            lsum += bsum;
        }

        // histogram
        if (tid < TM) atomicAdd(&chist[sidx[tid]], 1);

        // ---- quantized (out region starts at elem 1 -> scalar stores) ----
        float* out_q = out + OFF_Q;
        #pragma unroll 1
        for (int i = tid; i < TM * (Dm / 4); i += 256) {   // 32 iters
            int tok = i >> 6, f4 = i & 63;
            int k2 = sidx[tok];
            float4 e = *(const float4*)(emb + k2 * Dm + f4 * 4);
            float* qp = out_q + (size_t)(tb + tok) * Dm + f4 * 4;
            qp[0] = e.x; qp[1] = e.y; qp[2] = e.z; qp[3] = e.w;
        }

        // ---- one-hot encodings (region start == 2 mod 4 -> float2 ok) ----
        float* out_e = out + OFF_ENC;
        #pragma unroll 1
        for (int i = tid; i < TM * (Kc / 4); i += 256) {   // 16 iters
            int tok = i >> 5, f4 = i & 31;
            int k2 = sidx[tok];
            int d0 = f4 * 4;
            float2 v01, v23;
            v01.x = (d0 + 0 == k2) ? 1.f : 0.f;
            v01.y = (d0 + 1 == k2) ? 1.f : 0.f;
            v23.x = (d0 + 2 == k2) ? 1.f : 0.f;
            v23.y = (d0 + 3 == k2) ? 1.f : 0.f;
            float* ep = out_e + (size_t)(tb + tok) * Kc + d0;
            *(float2*)(ep)     = v01;
            *(float2*)(ep + 2) = v23;
        }

        if (tid < TM) out[OFF_IDX + tb + tid] = (float)sidx[tid];
        __syncthreads();   // protect sidx/xn2s/As for next tile
    }

    // ================= per-CTA results =================
    red[tid] = lsum;
    __syncthreads();
    #pragma unroll
    for (int s = 128; s > 0; s >>= 1) {
        if (tid < s) red[tid] += red[tid + s];
        __syncthreads();
    }
    if (tid == 0) g_partials[cta] = red[0];
    if (tid < Kc) g_hist[cta * Kc + tid] = chist[tid];

    __syncthreads();
    __threadfence();
    if (tid == 0) ticket[0] = atomicAdd(&g_done, 1);
    __syncthreads();

    // ================= last CTA: loss + perplexity =================
    if (ticket[0] == ncta - 1) {
        __threadfence();
        float term = 0.f;
        if (tid < Kc) {
            int cnt = 0;
            for (int b = 0; b < ncta; b++) cnt += g_hist[b * Kc + tid];
            float p = (float)cnt / (float)NTOK;
            term = p * logf(p + 1e-10f);
        }
        red[tid] = term;
        __syncthreads();
        #pragma unroll
        for (int s = 128; s > 0; s >>= 1) {
            if (tid < s) red[tid] += red[tid + s];
            __syncthreads();
        }
        float perp = expf(-red[0]);
        __syncthreads();

        red[tid] = (tid < ncta) ? g_partials[tid] : 0.f;
        __syncthreads();
        #pragma unroll
        for (int s = 128; s > 0; s >>= 1) {
            if (tid < s) red[tid] += red[tid + s];
            __syncthreads();
        }
        if (tid == 0) {
            out[0]        = 0.25f * red[0] / ((float)NTOK * (float)Dm);
            out[OFF_PERP] = perp;
            g_done = 0;                     // reset for next graph replay
        }
    }
}

// ---------------- launch ----------------
extern "C" void kernel_launch(void* const* d_in, const int* in_sizes, int n_in,
                              void* d_out, int out_size) {
    const float* inp = (const float*)d_in[0];   // [64,2048,256] f32
    const float* emb = (const float*)d_in[1];   // [128,256]     f32
    float* out = (float*)d_out;

    int nsm = 0;
    cudaDeviceGetAttribute(&nsm, cudaDevAttrMultiProcessorCount, 0);
    if (nsm <= 0) nsm = 148;
    if (nsm > MAXCTA) nsm = MAXCTA;
    if (nsm > NTILES) nsm = NTILES;

    cudaFuncSetAttribute(vq_kernel,
                         cudaFuncAttributeMaxDynamicSharedMemorySize, SMEM_BYTES);

    vq_kernel<<<nsm, 256, SMEM_BYTES>>>(inp, emb, out, nsm);
}